// round 11
// baseline (speedup 1.0000x reference)
#include <cuda_runtime.h>
#include <cstdint>

// ---------------------------------------------------------------------------
// Problem constants
// ---------------------------------------------------------------------------
#define N_ROWS 16384      // 64 * 256
#define N_FEAT 2048
#define N_BINS 32
#define NSTRIPE 1024               // one stripe per 16-row tile
#define TBL 65536
#define NTILE 128                  // 128-row tiles
#define NKQ 4                      // K split into quarters (512 cols each)
#define NG 64                      // 32-col groups over full K
#define NT16 (N_ROWS / 16)         // 1024 16-row fragments
// k_project dynamic smem: RP quarter 16KB + A block 64KB + soff
#define PROJ_SMEM (16384 + 65536 + 128)

// ---------------------------------------------------------------------------
// Scratch (static device globals; no runtime allocation)
// ---------------------------------------------------------------------------
__device__ __align__(16) unsigned int g_xpack8[(size_t)NT16 * NG * 32 * 4]; // e4m3 x (32MB)
__device__ float              g_psum[(size_t)NSTRIPE * N_FEAT];   // 8MB
__device__ float              g_psq [(size_t)NSTRIPE * N_FEAT];   // 8MB
__device__ float              g_isig[N_FEAT];
__device__ float              g_m2  [N_FEAT];              // mean * isig
__device__ float              g_off [N_BINS];              // 256 * (m2 . RP)
__device__ __align__(16) unsigned int g_rppack8[512 * 32]; // e4m3x4 256*isig*RP, swizzled
__device__ float              g_part[NKQ * N_ROWS * N_BINS]; // split-K partials
__device__ unsigned int       g_tilecnt[NTILE];            // arrival counters
__device__ unsigned int       g_hash[N_ROWS];
__device__ unsigned int       g_slot[N_ROWS];
__device__ unsigned long long g_tkey[TBL];
__device__ unsigned int       g_tcnt[TBL];

// ---------------------------------------------------------------------------
// Helpers
// ---------------------------------------------------------------------------
__device__ __forceinline__ unsigned pack8x4(float f0, float f1, float f2, float f3) {
    unsigned d;
    asm("{\n\t"
        ".reg .b16 lo, hi;\n\t"
        "cvt.rn.satfinite.e4m3x2.f32 lo, %2, %1;\n\t"
        "cvt.rn.satfinite.e4m3x2.f32 hi, %4, %3;\n\t"
        "mov.b32 %0, {lo, hi};\n\t"
        "}" : "=r"(d) : "f"(f0), "f"(f1), "f"(f2), "f"(f3));
    return d;
}

__device__ __forceinline__ void mma16832(float* c,
                                         unsigned a0, unsigned a1, unsigned a2, unsigned a3,
                                         unsigned b0, unsigned b1) {
    asm volatile(
        "mma.sync.aligned.m16n8k32.row.col.f32.e4m3.e4m3.f32 "
        "{%0,%1,%2,%3}, {%4,%5,%6,%7}, {%8,%9}, {%0,%1,%2,%3};"
        : "+f"(c[0]), "+f"(c[1]), "+f"(c[2]), "+f"(c[3])
        : "r"(a0), "r"(a1), "r"(a2), "r"(a3), "r"(b0), "r"(b1));
}

__device__ __forceinline__ uint32_t smaddr(const void* p) {
    return (uint32_t)__cvta_generic_to_shared(p);
}

__device__ __forceinline__ void cpa16(uint32_t dst, const void* src) {
    asm volatile("cp.async.cg.shared.global [%0], [%1], 16;" :: "r"(dst), "l"(src));
}

__device__ __forceinline__ void table_insert(int i, unsigned h) {
    unsigned long long key = ((unsigned long long)h << 6) | (unsigned long long)(i & 63);
    unsigned long long m = key * 0x9E3779B97F4A7C15ULL;
    unsigned s = (unsigned)(m >> 48);   // 16-bit slot
    for (;;) {
        unsigned long long prev = atomicCAS(&g_tkey[s], ~0ULL, key);
        if (prev == ~0ULL || prev == key) {
            atomicAdd(&g_tcnt[s], 1u);
            g_slot[i] = s;
            return;
        }
        s = (s + 1) & (TBL - 1);
    }
}

// ---------------------------------------------------------------------------
// Init kernels (split out so k_pre is the 4th launch -> gets profiled)
// ---------------------------------------------------------------------------
__global__ void k_initA() {           // hash-table keys
    g_tkey[blockIdx.x * 256 + threadIdx.x] = ~0ULL;
}
__global__ void k_initB() {           // hash-table counts
    g_tcnt[blockIdx.x * 256 + threadIdx.x] = 0u;
}
__global__ void k_initC() {           // tile arrival counters
    if (threadIdx.x < NTILE) g_tilecnt[threadIdx.x] = 0u;
}

// ---------------------------------------------------------------------------
// Kernel 4 (PROFILED): column partial sums + e4m3 fragment pack.
//   1024 blocks, one per tile16 (16 rows x 2048 cols = 128KB read, 32KB write).
//   Thread (g=tid>>2, qp=tid&3) owns 8 cols {g*32+4qp..+3, +16..+19}.
//   Per rr in 0..7: 4x LDG.128 (rows rr, rr+8; khalf 0/1) -> 1x STG.128
//   fragment word at uint4[(tile16*NG+g)*32 + rr*4 + qp]  (layout = R8/R9/R10).
//   Stats: per-thread 8-col accumulators over the 16 rows -> psum[tile16].
// ---------------------------------------------------------------------------
__global__ void __launch_bounds__(256, 4) k_pre(const float* __restrict__ x) {
    int b = blockIdx.x;                 // tile16
    int tid = threadIdx.x;
    int g = tid >> 2, qp = tid & 3;
    int f0 = g * 8 + qp;                // float4 slot, khalf=0
    int f1 = f0 + 4;                    // float4 slot, khalf=1
    const float4* x4 = (const float4*)x;
    uint4* xp4 = (uint4*)g_xpack8;

    size_t rbase = (size_t)b * 16 * 512;               // float4 units
    size_t wbase = ((size_t)b * NG + g) * 32 + qp;     // uint4 units

    float s[8], qq[8];
#pragma unroll
    for (int j = 0; j < 8; j++) { s[j] = 0.f; qq[j] = 0.f; }

#pragma unroll 2
    for (int rr = 0; rr < 8; rr++) {
        size_t rA = rbase + (size_t)rr * 512;
        size_t rB = rA + 8 * 512;
        float4 vA0 = x4[rA + f0];
        float4 vA1 = x4[rA + f1];
        float4 vB0 = x4[rB + f0];
        float4 vB1 = x4[rB + f1];

        s[0] += vA0.x + vB0.x; qq[0] += vA0.x*vA0.x + vB0.x*vB0.x;
        s[1] += vA0.y + vB0.y; qq[1] += vA0.y*vA0.y + vB0.y*vB0.y;
        s[2] += vA0.z + vB0.z; qq[2] += vA0.z*vA0.z + vB0.z*vB0.z;
        s[3] += vA0.w + vB0.w; qq[3] += vA0.w*vA0.w + vB0.w*vB0.w;
        s[4] += vA1.x + vB1.x; qq[4] += vA1.x*vA1.x + vB1.x*vB1.x;
        s[5] += vA1.y + vB1.y; qq[5] += vA1.y*vA1.y + vB1.y*vB1.y;
        s[6] += vA1.z + vB1.z; qq[6] += vA1.z*vA1.z + vB1.z*vB1.z;
        s[7] += vA1.w + vB1.w; qq[7] += vA1.w*vA1.w + vB1.w*vB1.w;

        uint4 w;
        w.x = pack8x4(vA0.x, vA0.y, vA0.z, vA0.w);
        w.y = pack8x4(vB0.x, vB0.y, vB0.z, vB0.w);
        w.z = pack8x4(vA1.x, vA1.y, vA1.z, vA1.w);
        w.w = pack8x4(vB1.x, vB1.y, vB1.z, vB1.w);
        xp4[wbase + (size_t)rr * 4] = w;
    }

    int c0 = g * 32 + qp * 4;
    *(float4*)(g_psum + (size_t)b * N_FEAT + c0)      = make_float4(s[0], s[1], s[2], s[3]);
    *(float4*)(g_psum + (size_t)b * N_FEAT + c0 + 16) = make_float4(s[4], s[5], s[6], s[7]);
    *(float4*)(g_psq  + (size_t)b * N_FEAT + c0)      = make_float4(qq[0], qq[1], qq[2], qq[3]);
    *(float4*)(g_psq  + (size_t)b * N_FEAT + c0 + 16) = make_float4(qq[4], qq[5], qq[6], qq[7]);
}

// ---------------------------------------------------------------------------
// Kernel 5: finalize RunningMeanStd -> isig, mean*isig
// ---------------------------------------------------------------------------
__global__ void k_stats() {
    __shared__ float ss[8][32], sq[8][32];
    int c = threadIdx.x & 31, g = threadIdx.x >> 5;
    int col = blockIdx.x * 32 + c;
    float s = 0.f, q = 0.f;
    for (int st = g; st < NSTRIPE; st += 8) {
        s += g_psum[(size_t)st * N_FEAT + col];
        q += g_psq [(size_t)st * N_FEAT + col];
    }
    ss[g][c] = s; sq[g][c] = q;
    __syncthreads();
    if (g == 0) {
#pragma unroll
        for (int j = 1; j < 8; j++) { s += ss[j][c]; q += sq[j][c]; }
        const float n = 16384.0f;
        float bm = s / n;
        float bv = (q - bm * bm * n) / (n - 1.0f);       // unbiased variance
        const double nd = 16384.0, totd = 1e-4 + nd;
        float mean = bm * (float)(nd / totd);
        float m2v  = (1e-4f + bv * 16384.0f) + (bm * bm) * (float)(1e-4 * nd / totd);
        float var  = m2v / (float)totd;
        float isg  = 1.0f / sqrtf(var + 1e-8f);
        g_isig[col] = isg;
        g_m2[col]   = mean * isg;
    }
}

// ---------------------------------------------------------------------------
// Kernel 6: RP'' = 256*isig*RP packed e4m3x4 swizzled (blocks 0..63);
//           off[b] = 256 * sum_k m2[k]*RP[k,b] (block 64, deterministic).
// ---------------------------------------------------------------------------
__global__ void k_scale(const float* __restrict__ rp) {
    if (blockIdx.x < 64) {
        int idx = blockIdx.x * 256 + threadIdx.x;  // 0..16383
        int k4 = idx >> 5;                         // 4-col k word 0..511
        int n  = idx & 31;
        float f0 = rp[(4 * k4 + 0) * N_BINS + n] * g_isig[4 * k4 + 0] * 256.0f;
        float f1 = rp[(4 * k4 + 1) * N_BINS + n] * g_isig[4 * k4 + 1] * 256.0f;
        float f2 = rp[(4 * k4 + 2) * N_BINS + n] * g_isig[4 * k4 + 2] * 256.0f;
        float f3 = rp[(4 * k4 + 3) * N_BINS + n] * g_isig[4 * k4 + 3] * 256.0f;
        int scol = n ^ ((k4 & 3) << 3);
        g_rppack8[k4 * 32 + scol] = pack8x4(f0, f1, f2, f3);
    } else {
        __shared__ float red[8][32];
        int b = threadIdx.x & 31, part = threadIdx.x >> 5;   // 8 parts x 256 k
        float s = 0.f;
        for (int k = part * 256; k < part * 256 + 256; k++)
            s = fmaf(g_m2[k], rp[k * N_BINS + b], s);
        red[part][b] = s;
        __syncthreads();
        if (part == 0) {
#pragma unroll
            for (int j = 1; j < 8; j++) s += red[j][b];
            g_off[b] = s * 256.0f;
        }
    }
}

// ---------------------------------------------------------------------------
// Kernel 7: quarter-K e4m3 mma projection (FROZEN from R10, measured 26.8us).
// ---------------------------------------------------------------------------
__global__ void __launch_bounds__(256, 2) k_project() {
    extern __shared__ unsigned smem[];
    unsigned* srp = smem;                        // [0,4096) words: RP quarter
    unsigned* sa  = smem + 4096;                 // [4096,20480) words: A 64KB
    float* soff   = (float*)(smem + 20480);      // [32]
    __shared__ int s_last;

    int tile = blockIdx.x >> 2;
    int kq   = blockIdx.x & 3;
    int tid  = threadIdx.x;

    {
        const char* src = (const char*)(g_rppack8 + kq * 4096);
        uint32_t dst = smaddr(srp);
#pragma unroll
        for (int i = 0; i < 4; i++) {
            int idx = tid + i * 256;
            cpa16(dst + idx * 16, src + idx * 16);
        }
    }
    {
        uint32_t dst = smaddr(sa);
#pragma unroll
        for (int i = 0; i < 16; i++) {
            int idx = tid + i * 256;          // 0..4095 (16B units)
            int w = idx >> 9, inner = idx & 511;
            const char* src = (const char*)g_xpack8 +
                (((size_t)(tile * 8 + w) * NG + kq * 16) * 512 + (size_t)inner * 16);
            cpa16(dst + idx * 16, src);
        }
    }
    if (tid < 32) soff[tid] = g_off[tid];
    asm volatile("cp.async.commit_group;");
    asm volatile("cp.async.wait_group 0;" ::: "memory");
    __syncthreads();

    int warp = tid >> 5, lane = tid & 31;
    int q = lane & 3, r = lane >> 2;
    int tile16 = tile * 8 + warp;
    int rowA = tile16 * 16 + r, rowB = rowA + 8;

    const uint4* ap = (const uint4*)sa + warp * 512 + lane;

    float acc[4][4];
#pragma unroll
    for (int t = 0; t < 4; t++)
#pragma unroll
        for (int c = 0; c < 4; c++) acc[t][c] = 0.f;

    unsigned scol[4];
#pragma unroll
    for (int t = 0; t < 4; t++) scol[t] = (unsigned)((t * 8 + r) ^ (q << 3));

#pragma unroll
    for (int g = 0; g < 16; g++) {               // 16 groups of 32 k-cols
        uint4 a = ap[g * 32];                    // fragment regs (LDS.128)
        int w0 = (g * 8 + q) * 32;
        int w1 = (g * 8 + q + 4) * 32;
#pragma unroll
        for (int t = 0; t < 4; t++) {
            unsigned b0 = srp[w0 + scol[t]];
            unsigned b1 = srp[w1 + scol[t]];
            mma16832(acc[t], a.x, a.y, a.z, a.w, b0, b1);
        }
    }

    float* dst = g_part + (size_t)kq * N_ROWS * N_BINS;
#pragma unroll
    for (int t = 0; t < 4; t++) {
        int cb = t * 8 + 2 * q;
        *(float2*)(dst + (size_t)rowA * N_BINS + cb) = make_float2(acc[t][0], acc[t][1]);
        *(float2*)(dst + (size_t)rowB * N_BINS + cb) = make_float2(acc[t][2], acc[t][3]);
    }
    __threadfence();
    if (tid == 0) s_last = (int)atomicAdd(&g_tilecnt[tile], 1u);
    __syncthreads();
    if (s_last != NKQ - 1) return;
    __threadfence();

    unsigned mlo = 0u, mhi = 0u;
#pragma unroll
    for (int t = 0; t < 4; t++) {
        int cb = t * 8 + 2 * q;
        float sA0 = acc[t][0], sA1 = acc[t][1];
        float sB0 = acc[t][2], sB1 = acc[t][3];
#pragma unroll
        for (int o = 0; o < NKQ; o++) {
            if (o == kq) continue;
            const float* src = g_part + (size_t)o * N_ROWS * N_BINS;
            float2 pa = *(const float2*)(src + (size_t)rowA * N_BINS + cb);
            float2 pb = *(const float2*)(src + (size_t)rowB * N_BINS + cb);
            sA0 += pa.x; sA1 += pa.y;
            sB0 += pb.x; sB1 += pb.y;
        }
        float o0 = soff[cb], o1 = soff[cb + 1];
        mlo |= ((sA0 - o0) > 0.f ? 1u : 0u) << cb;
        mlo |= ((sA1 - o1) > 0.f ? 1u : 0u) << (cb + 1);
        mhi |= ((sB0 - o0) > 0.f ? 1u : 0u) << cb;
        mhi |= ((sB1 - o1) > 0.f ? 1u : 0u) << (cb + 1);
    }
    mlo |= __shfl_xor_sync(0xffffffffu, mlo, 1);
    mlo |= __shfl_xor_sync(0xffffffffu, mlo, 2);
    mhi |= __shfl_xor_sync(0xffffffffu, mhi, 1);
    mhi |= __shfl_xor_sync(0xffffffffu, mhi, 2);

    if (q == 0) {
        g_hash[rowA] = mlo;
        g_hash[rowB] = mhi;
        table_insert(rowA, mlo);
        table_insert(rowB, mhi);
    }
}

// ---------------------------------------------------------------------------
// Kernel 8: rewards. Unique keys -> 1.0; rare duplicates get exact rank.
// ---------------------------------------------------------------------------
__global__ void k_final(float* __restrict__ out) {
    int i = blockIdx.x * 128 + threadIdx.x;
    unsigned s = g_slot[i];
    float v = 1.0f;
    if (g_tcnt[s] != 1u) {
        unsigned long long my = ((unsigned long long)g_hash[i] << 6) | (unsigned long long)(i & 63);
        int c = 1;
        for (int j = 0; j < i; j++) {
            unsigned long long kj = ((unsigned long long)g_hash[j] << 6) | (unsigned long long)(j & 63);
            c += (kj == my) ? 1 : 0;
        }
        v = 1.0f / sqrtf((float)c);
    }
    out[i] = v;
}

// ---------------------------------------------------------------------------
// Launch (k_pre is deliberately the 4th launch -> gets the ncu profile)
// ---------------------------------------------------------------------------
extern "C" void kernel_launch(void* const* d_in, const int* in_sizes, int n_in,
                              void* d_out, int out_size) {
    const float* x  = (const float*)d_in[0];
    const float* rp = (const float*)d_in[1];
    if (in_sizes[0] == N_FEAT * N_BINS) {   // defensive: swap if order differs
        const float* t = x; x = rp; rp = t;
    }
    float* out = (float*)d_out;

    cudaFuncSetAttribute(k_project, cudaFuncAttributeMaxDynamicSharedMemorySize, PROJ_SMEM);

    k_initA  <<<256, 256>>>();
    k_initB  <<<256, 256>>>();
    k_initC  <<<1, 128>>>();
    k_pre    <<<1024, 256>>>(x);
    k_stats  <<<64, 256>>>();
    k_scale  <<<65, 256>>>(rp);
    k_project<<<512, 256, PROJ_SMEM>>>();
    k_final  <<<128, 128>>>(out);
}

// round 12
// speedup vs baseline: 1.2043x; 1.2043x over previous
#include <cuda_runtime.h>
#include <cstdint>

// ---------------------------------------------------------------------------
// Problem constants
// ---------------------------------------------------------------------------
#define N_ROWS 16384      // 64 * 256
#define N_FEAT 2048
#define N_BINS 32
#define NSTRIPE 1024               // one stripe per 16-row tile
#define TBL 65536
#define NTILE 128                  // 128-row tiles
#define NKQ 4                      // K split into quarters (512 cols each)
#define NG 64                      // 32-col groups over full K
#define NT16 (N_ROWS / 16)         // 1024 16-row fragments
// k_project dynamic smem: RP quarter 16KB + A block 64KB + soff
#define PROJ_SMEM (16384 + 65536 + 128)

// ---------------------------------------------------------------------------
// Scratch (static device globals; no runtime allocation)
// ---------------------------------------------------------------------------
__device__ __align__(16) unsigned int g_xpack8[(size_t)NT16 * NG * 32 * 4]; // e4m3 x (32MB)
__device__ float              g_psum[(size_t)NSTRIPE * N_FEAT];   // 8MB
__device__ float              g_psq [(size_t)NSTRIPE * N_FEAT];   // 8MB
__device__ float              g_isig[N_FEAT];
__device__ float              g_m2  [N_FEAT];              // mean * isig
__device__ float              g_off [N_BINS];              // 256 * (m2 . RP)
__device__ __align__(16) unsigned int g_rppack8[512 * 32]; // e4m3x4 256*isig*RP, swizzled
__device__ float              g_part[NKQ * N_ROWS * N_BINS]; // split-K partials
__device__ unsigned int       g_tilecnt[NTILE];            // arrival counters
__device__ unsigned int       g_hash[N_ROWS];
__device__ unsigned int       g_slot[N_ROWS];
__device__ unsigned long long g_tkey[TBL];
__device__ unsigned int       g_tcnt[TBL];

// ---------------------------------------------------------------------------
// Helpers
// ---------------------------------------------------------------------------
__device__ __forceinline__ unsigned pack8x4(float f0, float f1, float f2, float f3) {
    unsigned d;
    asm("{\n\t"
        ".reg .b16 lo, hi;\n\t"
        "cvt.rn.satfinite.e4m3x2.f32 lo, %2, %1;\n\t"
        "cvt.rn.satfinite.e4m3x2.f32 hi, %4, %3;\n\t"
        "mov.b32 %0, {lo, hi};\n\t"
        "}" : "=r"(d) : "f"(f0), "f"(f1), "f"(f2), "f"(f3));
    return d;
}

__device__ __forceinline__ void mma16832(float* c,
                                         unsigned a0, unsigned a1, unsigned a2, unsigned a3,
                                         unsigned b0, unsigned b1) {
    asm volatile(
        "mma.sync.aligned.m16n8k32.row.col.f32.e4m3.e4m3.f32 "
        "{%0,%1,%2,%3}, {%4,%5,%6,%7}, {%8,%9}, {%0,%1,%2,%3};"
        : "+f"(c[0]), "+f"(c[1]), "+f"(c[2]), "+f"(c[3])
        : "r"(a0), "r"(a1), "r"(a2), "r"(a3), "r"(b0), "r"(b1));
}

__device__ __forceinline__ uint32_t smaddr(const void* p) {
    return (uint32_t)__cvta_generic_to_shared(p);
}

__device__ __forceinline__ void cpa16(uint32_t dst, const void* src) {
    asm volatile("cp.async.cg.shared.global [%0], [%1], 16;" :: "r"(dst), "l"(src));
}

__device__ __forceinline__ void table_insert(int i, unsigned h) {
    unsigned long long key = ((unsigned long long)h << 6) | (unsigned long long)(i & 63);
    unsigned long long m = key * 0x9E3779B97F4A7C15ULL;
    unsigned s = (unsigned)(m >> 48);   // 16-bit slot
    for (;;) {
        unsigned long long prev = atomicCAS(&g_tkey[s], ~0ULL, key);
        if (prev == ~0ULL || prev == key) {
            atomicAdd(&g_tcnt[s], 1u);
            g_slot[i] = s;
            return;
        }
        s = (s + 1) & (TBL - 1);
    }
}

// ---------------------------------------------------------------------------
// Kernel 1 (fused): column partial sums + e4m3 fragment pack + table inits.
//   blocks [0,1024): one per tile16 (16 rows x 2048 cols; 128KB rd, 32KB wr).
//     Thread (g=tid>>2, qp=tid&3) owns 8 cols {g*32+4qp..+3, +16..+19}.
//     Per rr in 0..7: 4x LDG.128 -> 1x STG.128 fragment word at
//     uint4[(tile16*NG+g)*32 + rr*4 + qp]  (layout unchanged since R8).
//   blocks [1024,1280): hash-table / tile-counter init.
// ---------------------------------------------------------------------------
__global__ void __launch_bounds__(256, 4) k_pre(const float* __restrict__ x) {
    int b = blockIdx.x;
    if (b < 1024) {
        int tid = threadIdx.x;
        int g = tid >> 2, qp = tid & 3;
        int f0 = g * 8 + qp;                // float4 slot, khalf=0
        int f1 = f0 + 4;                    // float4 slot, khalf=1
        const float4* x4 = (const float4*)x;
        uint4* xp4 = (uint4*)g_xpack8;

        size_t rbase = (size_t)b * 16 * 512;               // float4 units
        size_t wbase = ((size_t)b * NG + g) * 32 + qp;     // uint4 units

        float s[8], qq[8];
#pragma unroll
        for (int j = 0; j < 8; j++) { s[j] = 0.f; qq[j] = 0.f; }

#pragma unroll 2
        for (int rr = 0; rr < 8; rr++) {
            size_t rA = rbase + (size_t)rr * 512;
            size_t rB = rA + 8 * 512;
            float4 vA0 = x4[rA + f0];
            float4 vA1 = x4[rA + f1];
            float4 vB0 = x4[rB + f0];
            float4 vB1 = x4[rB + f1];

            s[0] += vA0.x + vB0.x; qq[0] += vA0.x*vA0.x + vB0.x*vB0.x;
            s[1] += vA0.y + vB0.y; qq[1] += vA0.y*vA0.y + vB0.y*vB0.y;
            s[2] += vA0.z + vB0.z; qq[2] += vA0.z*vA0.z + vB0.z*vB0.z;
            s[3] += vA0.w + vB0.w; qq[3] += vA0.w*vA0.w + vB0.w*vB0.w;
            s[4] += vA1.x + vB1.x; qq[4] += vA1.x*vA1.x + vB1.x*vB1.x;
            s[5] += vA1.y + vB1.y; qq[5] += vA1.y*vA1.y + vB1.y*vB1.y;
            s[6] += vA1.z + vB1.z; qq[6] += vA1.z*vA1.z + vB1.z*vB1.z;
            s[7] += vA1.w + vB1.w; qq[7] += vA1.w*vA1.w + vB1.w*vB1.w;

            uint4 w;
            w.x = pack8x4(vA0.x, vA0.y, vA0.z, vA0.w);
            w.y = pack8x4(vB0.x, vB0.y, vB0.z, vB0.w);
            w.z = pack8x4(vA1.x, vA1.y, vA1.z, vA1.w);
            w.w = pack8x4(vB1.x, vB1.y, vB1.z, vB1.w);
            xp4[wbase + (size_t)rr * 4] = w;
        }

        int c0 = g * 32 + qp * 4;
        *(float4*)(g_psum + (size_t)b * N_FEAT + c0)      = make_float4(s[0], s[1], s[2], s[3]);
        *(float4*)(g_psum + (size_t)b * N_FEAT + c0 + 16) = make_float4(s[4], s[5], s[6], s[7]);
        *(float4*)(g_psq  + (size_t)b * N_FEAT + c0)      = make_float4(qq[0], qq[1], qq[2], qq[3]);
        *(float4*)(g_psq  + (size_t)b * N_FEAT + c0 + 16) = make_float4(qq[4], qq[5], qq[6], qq[7]);
    } else {
        int i = (b - 1024) * 256 + threadIdx.x;
        g_tkey[i] = ~0ULL;
        g_tcnt[i] = 0u;
        if (b == 1024 && threadIdx.x < NTILE) g_tilecnt[threadIdx.x] = 0u;
    }
}

// ---------------------------------------------------------------------------
// Kernel 2: finalize RunningMeanStd -> isig, mean*isig.
//   256 blocks x 256: 8 cols/block, 32 threads/col (each sums 32 stripes).
//   Warp reads 4 stripes x 8 consecutive cols = 4 full 32B sectors.
// ---------------------------------------------------------------------------
__global__ void k_stats() {
    __shared__ float ss[32][8], sq[32][8];
    int c = threadIdx.x & 7, g = threadIdx.x >> 3;
    int col = blockIdx.x * 8 + c;
    float s = 0.f, q = 0.f;
#pragma unroll 4
    for (int st = g; st < NSTRIPE; st += 32) {
        s += g_psum[(size_t)st * N_FEAT + col];
        q += g_psq [(size_t)st * N_FEAT + col];
    }
    ss[g][c] = s; sq[g][c] = q;
    __syncthreads();
    if (g == 0) {
#pragma unroll
        for (int j = 1; j < 32; j++) { s += ss[j][c]; q += sq[j][c]; }
        const float n = 16384.0f;
        float bm = s / n;
        float bv = (q - bm * bm * n) / (n - 1.0f);       // unbiased variance
        const double nd = 16384.0, totd = 1e-4 + nd;
        float mean = bm * (float)(nd / totd);
        float m2v  = (1e-4f + bv * 16384.0f) + (bm * bm) * (float)(1e-4 * nd / totd);
        float var  = m2v / (float)totd;
        float isg  = 1.0f / sqrtf(var + 1e-8f);
        g_isig[col] = isg;
        g_m2[col]   = mean * isg;
    }
}

// ---------------------------------------------------------------------------
// Kernel 3: RP'' = 256*isig*RP packed e4m3x4 swizzled (blocks 0..63);
//           off[b] = 256 * sum_k m2[k]*RP[k,b] (block 64, deterministic).
// ---------------------------------------------------------------------------
__global__ void k_scale(const float* __restrict__ rp) {
    if (blockIdx.x < 64) {
        int idx = blockIdx.x * 256 + threadIdx.x;  // 0..16383
        int k4 = idx >> 5;                         // 4-col k word 0..511
        int n  = idx & 31;
        float f0 = rp[(4 * k4 + 0) * N_BINS + n] * g_isig[4 * k4 + 0] * 256.0f;
        float f1 = rp[(4 * k4 + 1) * N_BINS + n] * g_isig[4 * k4 + 1] * 256.0f;
        float f2 = rp[(4 * k4 + 2) * N_BINS + n] * g_isig[4 * k4 + 2] * 256.0f;
        float f3 = rp[(4 * k4 + 3) * N_BINS + n] * g_isig[4 * k4 + 3] * 256.0f;
        int scol = n ^ ((k4 & 3) << 3);
        g_rppack8[k4 * 32 + scol] = pack8x4(f0, f1, f2, f3);
    } else {
        __shared__ float red[8][32];
        int b = threadIdx.x & 31, part = threadIdx.x >> 5;   // 8 parts x 256 k
        float s = 0.f;
        for (int k = part * 256; k < part * 256 + 256; k++)
            s = fmaf(g_m2[k], rp[k * N_BINS + b], s);
        red[part][b] = s;
        __syncthreads();
        if (part == 0) {
#pragma unroll
            for (int j = 1; j < 8; j++) s += red[j][b];
            g_off[b] = s * 256.0f;
        }
    }
}

// ---------------------------------------------------------------------------
// Kernel 4 (4th launch, profiled): quarter-K e4m3 mma projection (FROZEN).
// ---------------------------------------------------------------------------
__global__ void __launch_bounds__(256, 2) k_project() {
    extern __shared__ unsigned smem[];
    unsigned* srp = smem;                        // [0,4096) words: RP quarter
    unsigned* sa  = smem + 4096;                 // [4096,20480) words: A 64KB
    float* soff   = (float*)(smem + 20480);      // [32]
    __shared__ int s_last;

    int tile = blockIdx.x >> 2;
    int kq   = blockIdx.x & 3;
    int tid  = threadIdx.x;

    {
        const char* src = (const char*)(g_rppack8 + kq * 4096);
        uint32_t dst = smaddr(srp);
#pragma unroll
        for (int i = 0; i < 4; i++) {
            int idx = tid + i * 256;
            cpa16(dst + idx * 16, src + idx * 16);
        }
    }
    {
        uint32_t dst = smaddr(sa);
#pragma unroll
        for (int i = 0; i < 16; i++) {
            int idx = tid + i * 256;          // 0..4095 (16B units)
            int w = idx >> 9, inner = idx & 511;
            const char* src = (const char*)g_xpack8 +
                (((size_t)(tile * 8 + w) * NG + kq * 16) * 512 + (size_t)inner * 16);
            cpa16(dst + idx * 16, src);
        }
    }
    if (tid < 32) soff[tid] = g_off[tid];
    asm volatile("cp.async.commit_group;");
    asm volatile("cp.async.wait_group 0;" ::: "memory");
    __syncthreads();

    int warp = tid >> 5, lane = tid & 31;
    int q = lane & 3, r = lane >> 2;
    int tile16 = tile * 8 + warp;
    int rowA = tile16 * 16 + r, rowB = rowA + 8;

    const uint4* ap = (const uint4*)sa + warp * 512 + lane;

    float acc[4][4];
#pragma unroll
    for (int t = 0; t < 4; t++)
#pragma unroll
        for (int c = 0; c < 4; c++) acc[t][c] = 0.f;

    unsigned scol[4];
#pragma unroll
    for (int t = 0; t < 4; t++) scol[t] = (unsigned)((t * 8 + r) ^ (q << 3));

#pragma unroll
    for (int g = 0; g < 16; g++) {               // 16 groups of 32 k-cols
        uint4 a = ap[g * 32];                    // fragment regs (LDS.128)
        int w0 = (g * 8 + q) * 32;
        int w1 = (g * 8 + q + 4) * 32;
#pragma unroll
        for (int t = 0; t < 4; t++) {
            unsigned b0 = srp[w0 + scol[t]];
            unsigned b1 = srp[w1 + scol[t]];
            mma16832(acc[t], a.x, a.y, a.z, a.w, b0, b1);
        }
    }

    float* dst = g_part + (size_t)kq * N_ROWS * N_BINS;
#pragma unroll
    for (int t = 0; t < 4; t++) {
        int cb = t * 8 + 2 * q;
        *(float2*)(dst + (size_t)rowA * N_BINS + cb) = make_float2(acc[t][0], acc[t][1]);
        *(float2*)(dst + (size_t)rowB * N_BINS + cb) = make_float2(acc[t][2], acc[t][3]);
    }
    __threadfence();
    if (tid == 0) s_last = (int)atomicAdd(&g_tilecnt[tile], 1u);
    __syncthreads();
    if (s_last != NKQ - 1) return;
    __threadfence();

    unsigned mlo = 0u, mhi = 0u;
#pragma unroll
    for (int t = 0; t < 4; t++) {
        int cb = t * 8 + 2 * q;
        float sA0 = acc[t][0], sA1 = acc[t][1];
        float sB0 = acc[t][2], sB1 = acc[t][3];
#pragma unroll
        for (int o = 0; o < NKQ; o++) {
            if (o == kq) continue;
            const float* src = g_part + (size_t)o * N_ROWS * N_BINS;
            float2 pa = *(const float2*)(src + (size_t)rowA * N_BINS + cb);
            float2 pb = *(const float2*)(src + (size_t)rowB * N_BINS + cb);
            sA0 += pa.x; sA1 += pa.y;
            sB0 += pb.x; sB1 += pb.y;
        }
        float o0 = soff[cb], o1 = soff[cb + 1];
        mlo |= ((sA0 - o0) > 0.f ? 1u : 0u) << cb;
        mlo |= ((sA1 - o1) > 0.f ? 1u : 0u) << (cb + 1);
        mhi |= ((sB0 - o0) > 0.f ? 1u : 0u) << cb;
        mhi |= ((sB1 - o1) > 0.f ? 1u : 0u) << (cb + 1);
    }
    mlo |= __shfl_xor_sync(0xffffffffu, mlo, 1);
    mlo |= __shfl_xor_sync(0xffffffffu, mlo, 2);
    mhi |= __shfl_xor_sync(0xffffffffu, mhi, 1);
    mhi |= __shfl_xor_sync(0xffffffffu, mhi, 2);

    if (q == 0) {
        g_hash[rowA] = mlo;
        g_hash[rowB] = mhi;
        table_insert(rowA, mlo);
        table_insert(rowB, mhi);
    }
}

// ---------------------------------------------------------------------------
// Kernel 5: rewards. Unique keys -> 1.0; rare duplicates get exact rank.
// ---------------------------------------------------------------------------
__global__ void k_final(float* __restrict__ out) {
    int i = blockIdx.x * 256 + threadIdx.x;
    unsigned s = g_slot[i];
    float v = 1.0f;
    if (g_tcnt[s] != 1u) {
        unsigned long long my = ((unsigned long long)g_hash[i] << 6) | (unsigned long long)(i & 63);
        int c = 1;
        for (int j = 0; j < i; j++) {
            unsigned long long kj = ((unsigned long long)g_hash[j] << 6) | (unsigned long long)(j & 63);
            c += (kj == my) ? 1 : 0;
        }
        v = 1.0f / sqrtf((float)c);
    }
    out[i] = v;
}

// ---------------------------------------------------------------------------
// Launch (5 launches; 4th = k_project gets the ncu profile)
// ---------------------------------------------------------------------------
extern "C" void kernel_launch(void* const* d_in, const int* in_sizes, int n_in,
                              void* d_out, int out_size) {
    const float* x  = (const float*)d_in[0];
    const float* rp = (const float*)d_in[1];
    if (in_sizes[0] == N_FEAT * N_BINS) {   // defensive: swap if order differs
        const float* t = x; x = rp; rp = t;
    }
    float* out = (float*)d_out;

    cudaFuncSetAttribute(k_project, cudaFuncAttributeMaxDynamicSharedMemorySize, PROJ_SMEM);

    k_pre    <<<1280, 256>>>(x);
    k_stats  <<<256, 256>>>();
    k_scale  <<<65, 256>>>(rp);
    k_project<<<512, 256, PROJ_SMEM>>>();
    k_final  <<<64, 256>>>(out);
}

// round 13
// speedup vs baseline: 1.3420x; 1.1143x over previous
#include <cuda_runtime.h>
#include <cstdint>

// ---------------------------------------------------------------------------
// Problem constants
// ---------------------------------------------------------------------------
#define N_ROWS 16384      // 64 * 256
#define N_FEAT 2048
#define N_BINS 32
#define NSTRIPE 1024               // one stripe per 16-row tile
#define TBL 65536
#define NTILE 128                  // 128-row tiles
#define NG 64                      // 32-col groups over full K
#define NT16 (N_ROWS / 16)         // 1024 16-row fragments
// k_project dynamic smem: RP full 64KB + 2 x 64KB A chunk buffers + soff
#define PROJ_SMEM (65536 * 3 + 128)   // 196736

// ---------------------------------------------------------------------------
// Scratch (static device globals; no runtime allocation)
// ---------------------------------------------------------------------------
__device__ __align__(16) unsigned int g_xpack8[(size_t)NT16 * NG * 32 * 4]; // e4m3 x (32MB)
__device__ float              g_psum[(size_t)NSTRIPE * N_FEAT];   // 8MB
__device__ float              g_psq [(size_t)NSTRIPE * N_FEAT];   // 8MB
__device__ float              g_isig[N_FEAT];
__device__ float              g_m2  [N_FEAT];              // mean * isig
__device__ float              g_off [N_BINS];              // 256 * (m2 . RP)
__device__ __align__(16) unsigned int g_rppack8[512 * 32]; // e4m3x4 256*isig*RP, swizzled
__device__ unsigned int       g_hash[N_ROWS];
__device__ unsigned int       g_slot[N_ROWS];
__device__ unsigned long long g_tkey[TBL];
__device__ unsigned int       g_tcnt[TBL];

// ---------------------------------------------------------------------------
// Helpers
// ---------------------------------------------------------------------------
__device__ __forceinline__ unsigned pack8x4(float f0, float f1, float f2, float f3) {
    unsigned d;
    asm("{\n\t"
        ".reg .b16 lo, hi;\n\t"
        "cvt.rn.satfinite.e4m3x2.f32 lo, %2, %1;\n\t"
        "cvt.rn.satfinite.e4m3x2.f32 hi, %4, %3;\n\t"
        "mov.b32 %0, {lo, hi};\n\t"
        "}" : "=r"(d) : "f"(f0), "f"(f1), "f"(f2), "f"(f3));
    return d;
}

__device__ __forceinline__ void mma16832(float* c,
                                         unsigned a0, unsigned a1, unsigned a2, unsigned a3,
                                         unsigned b0, unsigned b1) {
    asm volatile(
        "mma.sync.aligned.m16n8k32.row.col.f32.e4m3.e4m3.f32 "
        "{%0,%1,%2,%3}, {%4,%5,%6,%7}, {%8,%9}, {%0,%1,%2,%3};"
        : "+f"(c[0]), "+f"(c[1]), "+f"(c[2]), "+f"(c[3])
        : "r"(a0), "r"(a1), "r"(a2), "r"(a3), "r"(b0), "r"(b1));
}

__device__ __forceinline__ uint32_t smaddr(const void* p) {
    return (uint32_t)__cvta_generic_to_shared(p);
}

__device__ __forceinline__ void cpa16(uint32_t dst, const void* src) {
    asm volatile("cp.async.cg.shared.global [%0], [%1], 16;" :: "r"(dst), "l"(src));
}

template<int N> __device__ __forceinline__ void cpa_wait() {
    asm volatile("cp.async.wait_group %0;" :: "n"(N) : "memory");
}

__device__ __forceinline__ void table_insert(int i, unsigned h) {
    unsigned long long key = ((unsigned long long)h << 6) | (unsigned long long)(i & 63);
    unsigned long long m = key * 0x9E3779B97F4A7C15ULL;
    unsigned s = (unsigned)(m >> 48);   // 16-bit slot
    for (;;) {
        unsigned long long prev = atomicCAS(&g_tkey[s], ~0ULL, key);
        if (prev == ~0ULL || prev == key) {
            atomicAdd(&g_tcnt[s], 1u);
            g_slot[i] = s;
            return;
        }
        s = (s + 1) & (TBL - 1);
    }
}

// ---------------------------------------------------------------------------
// Kernel 1 (fused): column partial sums + e4m3 fragment pack + table inits.
//   blocks [0,1024): one per tile16 (FROZEN since R11, measured 28.4us).
//   blocks [1024,1280): hash-table init.
// ---------------------------------------------------------------------------
__global__ void __launch_bounds__(256, 4) k_pre(const float* __restrict__ x) {
    int b = blockIdx.x;
    if (b < 1024) {
        int tid = threadIdx.x;
        int g = tid >> 2, qp = tid & 3;
        int f0 = g * 8 + qp;                // float4 slot, khalf=0
        int f1 = f0 + 4;                    // float4 slot, khalf=1
        const float4* x4 = (const float4*)x;
        uint4* xp4 = (uint4*)g_xpack8;

        size_t rbase = (size_t)b * 16 * 512;               // float4 units
        size_t wbase = ((size_t)b * NG + g) * 32 + qp;     // uint4 units

        float s[8], qq[8];
#pragma unroll
        for (int j = 0; j < 8; j++) { s[j] = 0.f; qq[j] = 0.f; }

#pragma unroll 2
        for (int rr = 0; rr < 8; rr++) {
            size_t rA = rbase + (size_t)rr * 512;
            size_t rB = rA + 8 * 512;
            float4 vA0 = x4[rA + f0];
            float4 vA1 = x4[rA + f1];
            float4 vB0 = x4[rB + f0];
            float4 vB1 = x4[rB + f1];

            s[0] += vA0.x + vB0.x; qq[0] += vA0.x*vA0.x + vB0.x*vB0.x;
            s[1] += vA0.y + vB0.y; qq[1] += vA0.y*vA0.y + vB0.y*vB0.y;
            s[2] += vA0.z + vB0.z; qq[2] += vA0.z*vA0.z + vB0.z*vB0.z;
            s[3] += vA0.w + vB0.w; qq[3] += vA0.w*vA0.w + vB0.w*vB0.w;
            s[4] += vA1.x + vB1.x; qq[4] += vA1.x*vA1.x + vB1.x*vB1.x;
            s[5] += vA1.y + vB1.y; qq[5] += vA1.y*vA1.y + vB1.y*vB1.y;
            s[6] += vA1.z + vB1.z; qq[6] += vA1.z*vA1.z + vB1.z*vB1.z;
            s[7] += vA1.w + vB1.w; qq[7] += vA1.w*vA1.w + vB1.w*vB1.w;

            uint4 w;
            w.x = pack8x4(vA0.x, vA0.y, vA0.z, vA0.w);
            w.y = pack8x4(vB0.x, vB0.y, vB0.z, vB0.w);
            w.z = pack8x4(vA1.x, vA1.y, vA1.z, vA1.w);
            w.w = pack8x4(vB1.x, vB1.y, vB1.z, vB1.w);
            xp4[wbase + (size_t)rr * 4] = w;
        }

        int c0 = g * 32 + qp * 4;
        *(float4*)(g_psum + (size_t)b * N_FEAT + c0)      = make_float4(s[0], s[1], s[2], s[3]);
        *(float4*)(g_psum + (size_t)b * N_FEAT + c0 + 16) = make_float4(s[4], s[5], s[6], s[7]);
        *(float4*)(g_psq  + (size_t)b * N_FEAT + c0)      = make_float4(qq[0], qq[1], qq[2], qq[3]);
        *(float4*)(g_psq  + (size_t)b * N_FEAT + c0 + 16) = make_float4(qq[4], qq[5], qq[6], qq[7]);
    } else {
        int i = (b - 1024) * 256 + threadIdx.x;
        g_tkey[i] = ~0ULL;
        g_tcnt[i] = 0u;
    }
}

// ---------------------------------------------------------------------------
// Kernel 2: finalize RunningMeanStd -> isig, mean*isig (FROZEN from R12).
// ---------------------------------------------------------------------------
__global__ void k_stats() {
    __shared__ float ss[32][8], sq[32][8];
    int c = threadIdx.x & 7, g = threadIdx.x >> 3;
    int col = blockIdx.x * 8 + c;
    float s = 0.f, q = 0.f;
#pragma unroll 4
    for (int st = g; st < NSTRIPE; st += 32) {
        s += g_psum[(size_t)st * N_FEAT + col];
        q += g_psq [(size_t)st * N_FEAT + col];
    }
    ss[g][c] = s; sq[g][c] = q;
    __syncthreads();
    if (g == 0) {
#pragma unroll
        for (int j = 1; j < 32; j++) { s += ss[j][c]; q += sq[j][c]; }
        const float n = 16384.0f;
        float bm = s / n;
        float bv = (q - bm * bm * n) / (n - 1.0f);       // unbiased variance
        const double nd = 16384.0, totd = 1e-4 + nd;
        float mean = bm * (float)(nd / totd);
        float m2v  = (1e-4f + bv * 16384.0f) + (bm * bm) * (float)(1e-4 * nd / totd);
        float var  = m2v / (float)totd;
        float isg  = 1.0f / sqrtf(var + 1e-8f);
        g_isig[col] = isg;
        g_m2[col]   = mean * isg;
    }
}

// ---------------------------------------------------------------------------
// Kernel 3: RP'' = 256*isig*RP packed e4m3x4 swizzled (blocks 0..63);
//           off[b] = 256 * sum_k m2[k]*RP[k,b] (block 64, deterministic).
// ---------------------------------------------------------------------------
__global__ void k_scale(const float* __restrict__ rp) {
    if (blockIdx.x < 64) {
        int idx = blockIdx.x * 256 + threadIdx.x;  // 0..16383
        int k4 = idx >> 5;                         // 4-col k word 0..511
        int n  = idx & 31;
        float f0 = rp[(4 * k4 + 0) * N_BINS + n] * g_isig[4 * k4 + 0] * 256.0f;
        float f1 = rp[(4 * k4 + 1) * N_BINS + n] * g_isig[4 * k4 + 1] * 256.0f;
        float f2 = rp[(4 * k4 + 2) * N_BINS + n] * g_isig[4 * k4 + 2] * 256.0f;
        float f3 = rp[(4 * k4 + 3) * N_BINS + n] * g_isig[4 * k4 + 3] * 256.0f;
        int scol = n ^ ((k4 & 3) << 3);
        g_rppack8[k4 * 32 + scol] = pack8x4(f0, f1, f2, f3);
    } else {
        __shared__ float red[8][32];
        int b = threadIdx.x & 31, part = threadIdx.x >> 5;   // 8 parts x 256 k
        float s = 0.f;
        for (int k = part * 256; k < part * 256 + 256; k++)
            s = fmaf(g_m2[k], rp[k * N_BINS + b], s);
        red[part][b] = s;
        __syncthreads();
        if (part == 0) {
#pragma unroll
            for (int j = 1; j < 8; j++) s += red[j][b];
            g_off[b] = s * 256.0f;
        }
    }
}

// ---------------------------------------------------------------------------
// Kernel 4: FULL-K e4m3 mma projection, one block per 128-row tile.
//   128 blocks = ONE wave. No split-K: no partials, no atomics, no combine.
//   smem: RP full 64KB + A double buffer 2x64KB (chunk = 512 k-cols).
//   Pipeline: stage RP+A0 | A1, then per chunk: wait -> compute -> stage k+2.
//   Tail per block: offset-subtract + sign -> hash -> table insert.
// ---------------------------------------------------------------------------
__global__ void __launch_bounds__(256, 1) k_project() {
    extern __shared__ unsigned smem[];
    unsigned* srp = smem;                        // [0,16384) words: RP full
    unsigned* sa0 = smem + 16384;                // A buffer 0 (16384 words)
    unsigned* sa1 = smem + 32768;                // A buffer 1
    float* soff   = (float*)(smem + 49152);      // [32]

    int tile = blockIdx.x;
    int tid  = threadIdx.x;

    // stage RP full (4096 x 16B) + A chunk 0 -> group 0
    {
        const char* src = (const char*)g_rppack8;
        uint32_t dst = smaddr(srp);
#pragma unroll
        for (int i = 0; i < 16; i++) {
            int idx = tid + i * 256;
            cpa16(dst + idx * 16, src + idx * 16);
        }
    }
    // A chunk staging helper pattern: chunk kq into buffer buf
    //   idx in [0,4096): w = idx>>9 (warp), inner = idx&511
    //   src = xpack8 + ((tile*8+w)*NG + kq*16)*512B + inner*16B
    {
        uint32_t dst = smaddr(sa0);
#pragma unroll
        for (int i = 0; i < 16; i++) {
            int idx = tid + i * 256;
            int w = idx >> 9, inner = idx & 511;
            const char* src = (const char*)g_xpack8 +
                (((size_t)(tile * 8 + w) * NG + 0 * 16) * 512 + (size_t)inner * 16);
            cpa16(dst + idx * 16, src);
        }
    }
    if (tid < 32) soff[tid] = g_off[tid];
    asm volatile("cp.async.commit_group;");
    // A chunk 1 -> group 1
    {
        uint32_t dst = smaddr(sa1);
#pragma unroll
        for (int i = 0; i < 16; i++) {
            int idx = tid + i * 256;
            int w = idx >> 9, inner = idx & 511;
            const char* src = (const char*)g_xpack8 +
                (((size_t)(tile * 8 + w) * NG + 1 * 16) * 512 + (size_t)inner * 16);
            cpa16(dst + idx * 16, src);
        }
    }
    asm volatile("cp.async.commit_group;");

    int warp = tid >> 5, lane = tid & 31;
    int q = lane & 3, r = lane >> 2;
    int tile16 = tile * 8 + warp;
    int rowA = tile16 * 16 + r, rowB = rowA + 8;

    float acc[4][4];
#pragma unroll
    for (int t = 0; t < 4; t++)
#pragma unroll
        for (int c = 0; c < 4; c++) acc[t][c] = 0.f;

    unsigned scol[4];
#pragma unroll
    for (int t = 0; t < 4; t++) scol[t] = (unsigned)((t * 8 + r) ^ (q << 3));

#pragma unroll
    for (int kq = 0; kq < 4; kq++) {
        if (kq < 3) cpa_wait<1>(); else cpa_wait<0>();
        __syncthreads();

        unsigned* sa = (kq & 1) ? sa1 : sa0;
        const uint4* ap = (const uint4*)sa + warp * 512 + lane;
#pragma unroll
        for (int gg = 0; gg < 16; gg++) {            // 16 groups of 32 k-cols
            uint4 a = ap[gg * 32];                   // fragment regs (LDS.128)
            int g = kq * 16 + gg;
            int w0 = (g * 8 + q) * 32;
            int w1 = (g * 8 + q + 4) * 32;
#pragma unroll
            for (int t = 0; t < 4; t++) {
                unsigned b0 = srp[w0 + scol[t]];
                unsigned b1 = srp[w1 + scol[t]];
                mma16832(acc[t], a.x, a.y, a.z, a.w, b0, b1);
            }
        }
        __syncthreads();

        if (kq < 2) {    // stage chunk kq+2 into the buffer just freed
            unsigned* dstbuf = (kq & 1) ? sa1 : sa0;
            uint32_t dst = smaddr(dstbuf);
            int kn = kq + 2;
#pragma unroll
            for (int i = 0; i < 16; i++) {
                int idx = tid + i * 256;
                int w = idx >> 9, inner = idx & 511;
                const char* src = (const char*)g_xpack8 +
                    (((size_t)(tile * 8 + w) * NG + kn * 16) * 512 + (size_t)inner * 16);
                cpa16(dst + idx * 16, src);
            }
            asm volatile("cp.async.commit_group;");
        }
    }

    // full-K accumulators -> offset-subtract -> sign bits -> hash -> insert
    unsigned mlo = 0u, mhi = 0u;
#pragma unroll
    for (int t = 0; t < 4; t++) {
        int cb = t * 8 + 2 * q;
        float o0 = soff[cb], o1 = soff[cb + 1];
        mlo |= ((acc[t][0] - o0) > 0.f ? 1u : 0u) << cb;
        mlo |= ((acc[t][1] - o1) > 0.f ? 1u : 0u) << (cb + 1);
        mhi |= ((acc[t][2] - o0) > 0.f ? 1u : 0u) << cb;
        mhi |= ((acc[t][3] - o1) > 0.f ? 1u : 0u) << (cb + 1);
    }
    mlo |= __shfl_xor_sync(0xffffffffu, mlo, 1);
    mlo |= __shfl_xor_sync(0xffffffffu, mlo, 2);
    mhi |= __shfl_xor_sync(0xffffffffu, mhi, 1);
    mhi |= __shfl_xor_sync(0xffffffffu, mhi, 2);

    if (q == 0) {
        g_hash[rowA] = mlo;
        g_hash[rowB] = mhi;
        table_insert(rowA, mlo);
        table_insert(rowB, mhi);
    }
}

// ---------------------------------------------------------------------------
// Kernel 5: rewards. Unique keys -> 1.0; rare duplicates get exact rank.
// ---------------------------------------------------------------------------
__global__ void k_final(float* __restrict__ out) {
    int i = blockIdx.x * 256 + threadIdx.x;
    unsigned s = g_slot[i];
    float v = 1.0f;
    if (g_tcnt[s] != 1u) {
        unsigned long long my = ((unsigned long long)g_hash[i] << 6) | (unsigned long long)(i & 63);
        int c = 1;
        for (int j = 0; j < i; j++) {
            unsigned long long kj = ((unsigned long long)g_hash[j] << 6) | (unsigned long long)(j & 63);
            c += (kj == my) ? 1 : 0;
        }
        v = 1.0f / sqrtf((float)c);
    }
    out[i] = v;
}

// ---------------------------------------------------------------------------
// Launch (5 launches; 4th = k_project gets the ncu profile)
// ---------------------------------------------------------------------------
extern "C" void kernel_launch(void* const* d_in, const int* in_sizes, int n_in,
                              void* d_out, int out_size) {
    const float* x  = (const float*)d_in[0];
    const float* rp = (const float*)d_in[1];
    if (in_sizes[0] == N_FEAT * N_BINS) {   // defensive: swap if order differs
        const float* t = x; x = rp; rp = t;
    }
    float* out = (float*)d_out;

    cudaFuncSetAttribute(k_project, cudaFuncAttributeMaxDynamicSharedMemorySize, PROJ_SMEM);

    k_pre    <<<1280, 256>>>(x);
    k_stats  <<<256, 256>>>();
    k_scale  <<<65, 256>>>(rp);
    k_project<<<NTILE, 256, PROJ_SMEM>>>();
    k_final  <<<64, 256>>>(out);
}